// round 4
// baseline (speedup 1.0000x reference)
#include <cuda_runtime.h>
#include <cstdint>

// Shapes
#define NB   8
#define NTOK 8192      // N * I * J
#define XD   256
#define RD   256
#define UD   64
#define VD   64
#define HD   128

// Scratch (allocation-free: __device__ globals)
__device__ float g_t[NB * RD * HD];        // t[n,r,h]
__device__ float g_v[NTOK * HD];           // v[tok,h]
__device__ float g_w2t[XD * VD * HD];      // rna-rounded-to-tf32 copy of w2 (8MB)
__device__ float g_part[2][NTOK * VD];     // K-split partial sums (4MB)

// ---------------------------------------------------------------------------
// Kernel W: g_w2t = round_to_nearest_tf32(w2). Unbiased rounding once, so the
// tensor-core path has no truncation bias.
// ---------------------------------------------------------------------------
__global__ void kW(const float* __restrict__ w2) {
    int i = (blockIdx.x * 256 + threadIdx.x) * 4;
    float4 v = *reinterpret_cast<const float4*>(w2 + i);
    uint32_t r0, r1, r2, r3;
    asm("cvt.rna.tf32.f32 %0, %1;" : "=r"(r0) : "f"(v.x));
    asm("cvt.rna.tf32.f32 %0, %1;" : "=r"(r1) : "f"(v.y));
    asm("cvt.rna.tf32.f32 %0, %1;" : "=r"(r2) : "f"(v.z));
    asm("cvt.rna.tf32.f32 %0, %1;" : "=r"(r3) : "f"(v.w));
    float4 o;
    o.x = __uint_as_float(r0); o.y = __uint_as_float(r1);
    o.z = __uint_as_float(r2); o.w = __uint_as_float(r3);
    *reinterpret_cast<float4*>(g_w2t + i) = o;
}

// ---------------------------------------------------------------------------
// Kernel A: t[n,r,h] = sum_u ( sum_v u[n,r,u,v] ) * w1[r,u,h]
// ---------------------------------------------------------------------------
__global__ void kA(const float* __restrict__ u, const float* __restrict__ w1) {
    const int n   = blockIdx.x >> 8;
    const int rr  = blockIdx.x & 255;
    const int tid = threadIdx.x;            // 0..127

    __shared__ float us[UD * VD];
    __shared__ float s[UD];

    const float* ub = u + (size_t)(n * RD + rr) * (UD * VD);
    for (int i = tid; i < UD * VD; i += 128) us[i] = ub[i];
    __syncthreads();

    if (tid < UD) {
        float acc = 0.f;
        #pragma unroll 8
        for (int v = 0; v < VD; v++)
            acc += us[tid * VD + ((v + tid) & (VD - 1))];
        s[tid] = acc;
    }
    __syncthreads();

    float acc = 0.f;
    const float* w1b = w1 + (size_t)rr * UD * HD + tid;   // h = tid, coalesced
    #pragma unroll 8
    for (int uu = 0; uu < UD; uu++)
        acc += s[uu] * w1b[uu * HD];
    g_t[(n * RD + rr) * HD + tid] = acc;
}

// ---------------------------------------------------------------------------
// Kernel B: v[tok,h] = relu( sum_r r[tok,rr] * t[n,rr,h] )
// ---------------------------------------------------------------------------
__global__ void kB(const float* __restrict__ r) {
    const int b    = blockIdx.x;
    const int tid  = threadIdx.x;           // h
    const int tok0 = b * 16;
    const int n    = tok0 >> 10;

    __shared__ float rs[16 * RD];
    const float* rb = r + (size_t)tok0 * RD;
    for (int i = tid; i < 16 * RD; i += 128) rs[i] = rb[i];
    __syncthreads();

    float acc[16];
    #pragma unroll
    for (int t = 0; t < 16; t++) acc[t] = 0.f;

    const float* tb = g_t + (size_t)n * RD * HD + tid;
    for (int rr = 0; rr < RD; rr += 4) {
        const float w0  = tb[(rr + 0) * HD];
        const float w1v = tb[(rr + 1) * HD];
        const float w2v = tb[(rr + 2) * HD];
        const float w3v = tb[(rr + 3) * HD];
        #pragma unroll
        for (int t = 0; t < 16; t++) {
            float4 rv = *reinterpret_cast<const float4*>(&rs[t * RD + rr]);
            acc[t] += rv.x * w0 + rv.y * w1v + rv.z * w2v + rv.w * w3v;
        }
    }
    #pragma unroll
    for (int t = 0; t < 16; t++)
        g_v[(size_t)(tok0 + t) * HD + tid] = fmaxf(acc[t], 0.f);
}

// ---------------------------------------------------------------------------
// Kernel C (dominant, tensor cores):
//   out[t,vv] = sum_{x,h} (x[t,x]*v[t,h]) * w2[x,vv,h]
// GEMM M=8192, N=64, K=32768 via mma.sync.m16n8k8.tf32.
// A fragments generated in registers per x0 (rank-1: x[t,x0] * v[t,h]);
// v fragments hoisted into registers (x0-invariant).
// B tile per x0 = w2[x0] (native [64,128] row-major = B^T), cp.async
// double-buffered. Grid = 64 token-tiles (128 tok) x 2 K-splits over x.
// ---------------------------------------------------------------------------
#define XS 132   // padded row stride (floats) for x tile
#define BS 132   // padded row stride (floats) for w2 tile

__global__ __launch_bounds__(256, 1) void kC(const float* __restrict__ x) {
    extern __shared__ float sm[];
    float* xs  = sm;                   // 128 x 132
    float* b0s = xs + 128 * XS;        // 64 x 132
    float* b1s = b0s + 64 * BS;        // 64 x 132
    float* vs  = b1s + 64 * BS;        // 128 x 128

    const int tid   = threadIdx.x;
    const int split = blockIdx.x >> 6;        // 0/1 : x-range half
    const int tile  = blockIdx.x & 63;        // token tile
    const int tok0  = tile * 128;
    const int xbase = split * 128;

    // Stage x half-tile [128 tok x 128 x] and v tile [128 tok x 128 h]
    {
        const float4* xg = reinterpret_cast<const float4*>(x + (size_t)tok0 * XD + xbase);
        #pragma unroll
        for (int j = 0; j < 16; j++) {
            int idx = tid + j * 256;          // 0..4095 float4
            int row = idx >> 5, c4 = idx & 31;
            float4 val = xg[row * (XD / 4) + c4];
            *reinterpret_cast<float4*>(&xs[row * XS + c4 * 4]) = val;
        }
        const float4* vg = reinterpret_cast<const float4*>(g_v + (size_t)tok0 * HD);
        #pragma unroll
        for (int j = 0; j < 16; j++) {
            int idx = tid + j * 256;
            reinterpret_cast<float4*>(vs)[idx] = vg[idx];
        }
    }
    __syncthreads();

    const int lane = tid & 31, warp = tid >> 5;
    const int g  = lane >> 2, kl = lane & 3;
    const int ta = warp * 16 + g;             // A rows handled by this thread
    const int tb2 = ta + 8;

    // Hoist v fragments (x0-invariant): 64 registers
    float va0[16], va4[16], vb0[16], vb4[16];
    #pragma unroll
    for (int hc = 0; hc < 16; hc++) {
        int h = hc * 8;
        va0[hc] = vs[ta  * HD + h + kl];
        va4[hc] = vs[ta  * HD + h + kl + 4];
        vb0[hc] = vs[tb2 * HD + h + kl];
        vb4[hc] = vs[tb2 * HD + h + kl + 4];
    }

    float c[8][4];
    #pragma unroll
    for (int nt = 0; nt < 8; nt++) {
        c[nt][0] = 0.f; c[nt][1] = 0.f; c[nt][2] = 0.f; c[nt][3] = 0.f;
    }

    // cp.async loader for w2[x0] tile: 8192 floats -> padded 64x132
    auto cpB = [&](int x0, float* dst) {
        const float* src = g_w2t + (size_t)(xbase + x0) * (VD * HD);
        #pragma unroll
        for (int j = 0; j < 8; j++) {
            int idx = tid + j * 256;          // 0..2047 float4
            int row = idx >> 5, c4 = idx & 31;
            uint32_t daddr = (uint32_t)__cvta_generic_to_shared(&dst[row * BS + c4 * 4]);
            asm volatile("cp.async.cg.shared.global [%0], [%1], 16;\n"
                         :: "r"(daddr), "l"(src + idx * 4) : "memory");
        }
    };

    cpB(0, b0s);
    asm volatile("cp.async.commit_group;\n" ::: "memory");

    for (int x0 = 0; x0 < 128; x0++) {
        if (x0 + 1 < 128) cpB(x0 + 1, ((x0 + 1) & 1) ? b1s : b0s);
        asm volatile("cp.async.commit_group;\n" ::: "memory");
        asm volatile("cp.async.wait_group 1;\n" ::: "memory");
        __syncthreads();

        const uint32_t* Bu = reinterpret_cast<const uint32_t*>((x0 & 1) ? b1s : b0s);
        const float xa = xs[ta  * XS + x0];
        const float xb = xs[tb2 * XS + x0];

        #pragma unroll
        for (int hc = 0; hc < 16; hc++) {
            // A fragment: A[t, kk] = x[t,x0] * v[t, hc*8+kk], rna-rounded (unbiased)
            float f0 = xa * va0[hc];
            float f1 = xb * vb0[hc];
            float f2 = xa * va4[hc];
            float f3 = xb * vb4[hc];
            uint32_t A0, A1, A2, A3;
            asm("cvt.rna.tf32.f32 %0, %1;" : "=r"(A0) : "f"(f0));
            asm("cvt.rna.tf32.f32 %0, %1;" : "=r"(A1) : "f"(f1));
            asm("cvt.rna.tf32.f32 %0, %1;" : "=r"(A2) : "f"(f2));
            asm("cvt.rna.tf32.f32 %0, %1;" : "=r"(A3) : "f"(f3));

            #pragma unroll
            for (int nt = 0; nt < 8; nt++) {
                uint32_t B0 = Bu[(nt * 8 + g) * BS + hc * 8 + kl];
                uint32_t B1 = Bu[(nt * 8 + g) * BS + hc * 8 + kl + 4];
                asm volatile(
                    "mma.sync.aligned.m16n8k8.row.col.f32.tf32.tf32.f32 "
                    "{%0,%1,%2,%3}, {%4,%5,%6,%7}, {%8,%9}, {%0,%1,%2,%3};\n"
                    : "+f"(c[nt][0]), "+f"(c[nt][1]), "+f"(c[nt][2]), "+f"(c[nt][3])
                    : "r"(A0), "r"(A1), "r"(A2), "r"(A3), "r"(B0), "r"(B1));
            }
        }
        __syncthreads();   // protect the buffer refilled next iteration
    }

    // Epilogue: write partials (row ta cols nt*8+2*kl(+1); row ta+8 same cols)
    float* pp = g_part[split];
    #pragma unroll
    for (int nt = 0; nt < 8; nt++) {
        int col = nt * 8 + kl * 2;
        *reinterpret_cast<float2*>(&pp[(size_t)(tok0 + ta)  * VD + col]) =
            make_float2(c[nt][0], c[nt][1]);
        *reinterpret_cast<float2*>(&pp[(size_t)(tok0 + tb2) * VD + col]) =
            make_float2(c[nt][2], c[nt][3]);
    }
}

// ---------------------------------------------------------------------------
// Kernel D: out = part0 + part1 (deterministic K-split combine)
// ---------------------------------------------------------------------------
__global__ void kD(float* __restrict__ out) {
    int i = blockIdx.x * 256 + threadIdx.x;   // float4 index
    float4 a = reinterpret_cast<const float4*>(g_part[0])[i];
    float4 b = reinterpret_cast<const float4*>(g_part[1])[i];
    float4 o;
    o.x = a.x + b.x; o.y = a.y + b.y; o.z = a.z + b.z; o.w = a.w + b.w;
    reinterpret_cast<float4*>(out)[i] = o;
}

// ---------------------------------------------------------------------------
extern "C" void kernel_launch(void* const* d_in, const int* in_sizes, int n_in,
                              void* d_out, int out_size) {
    const float* x  = (const float*)d_in[0];
    const float* r  = (const float*)d_in[1];
    const float* u  = (const float*)d_in[2];
    const float* w1 = (const float*)d_in[3];
    const float* w2 = (const float*)d_in[4];
    float* out = (float*)d_out;

    const int kc_smem = (128 * XS + 2 * 64 * BS + 128 * HD) * (int)sizeof(float);
    cudaFuncSetAttribute(kC, cudaFuncAttributeMaxDynamicSharedMemorySize, kc_smem);

    kW<<<(XD * VD * HD) / 1024, 256>>>(w2);
    kA<<<NB * RD, 128>>>(u, w1);
    kB<<<NTOK / 16, 128>>>(r);
    kC<<<128, 256, kc_smem>>>(x);
    kD<<<(NTOK * VD) / 1024, 256>>>(out);
}

// round 6
// speedup vs baseline: 1.3940x; 1.3940x over previous
#include <cuda_runtime.h>
#include <cuda_fp16.h>
#include <cstdint>

// Shapes
#define NB   8
#define NTOK 8192      // N * I * J
#define XD   256
#define RD   256
#define UD   64
#define VD   64
#define HD   128

// Scratch (allocation-free: __device__ globals)
__device__ float  g_t[NB * RD * HD];         // t[n,r,h]
__device__ float  g_v[NTOK * HD];            // v[tok,h]
__device__ __half g_w2h[XD * VD * HD];       // fragment-packed fp16 w2 * 1024 (4MB)
__device__ float  g_part[2][NTOK * VD];      // K-split partial sums (scaled by 1024)

// pack two f32 -> f16x2 (round-to-nearest-even): d = {lo, hi}
#define PACK_H2(d, lo, hi) \
    asm("cvt.rn.f16x2.f32 %0, %1, %2;" : "=r"(d) : "f"(hi), "f"(lo))

// ---------------------------------------------------------------------------
// Kernel W: fragment-pack w2 for kC.
// Consumer thread (g=lane>>2, kl=lane&3) at (x0, half, hcp, nt) does one
// LDS.128 = 8 fp16 covering mma B-fragments for chunks ch=2*hcp{,+1}:
//   {ch0:B[2kl],B[2kl+1], ch0:B[2kl+8],B[2kl+9], ch1:..., ch1:...}
// Byte addr = x0*16384 + half*8192 + hcp*4096 + vv*64 + kl*16 + slot*2.
// Values scaled by 2^10 (exact) to clear fp16 subnormal range.
// ---------------------------------------------------------------------------
__global__ void kW(const float* __restrict__ w2) {
    int idx = blockIdx.x * 256 + threadIdx.x;      // float4 over w2, h fastest
    float4 v = reinterpret_cast<const float4*>(w2)[idx];
    float e[4] = { v.x, v.y, v.z, v.w };
    int h0 = (idx << 2) & (HD - 1);
    int vv = (idx >> 5) & (VD - 1);
    int x0 = idx >> 11;
    char* base = reinterpret_cast<char*>(g_w2h);
    #pragma unroll
    for (int q = 0; q < 4; q++) {
        int h    = h0 + q;
        int half = h >> 6, hr = h & 63;
        int ch   = hr >> 4, kk = hr & 15;
        int breg = kk >> 3, kk2 = kk & 7;
        int kl   = kk2 >> 1, dlt = kk2 & 1;
        int hcp  = ch >> 1, codd = ch & 1;
        int slot = codd * 4 + breg * 2 + dlt;
        size_t off = (size_t)x0 * 16384 + half * 8192 + hcp * 4096
                   + vv * 64 + kl * 16 + slot * 2;
        *reinterpret_cast<__half*>(base + off) = __float2half_rn(e[q] * 1024.0f);
    }
}

// ---------------------------------------------------------------------------
// Kernel A: t[n,r,h] = sum_u ( sum_v u[n,r,u,v] ) * w1[r,u,h]
// ---------------------------------------------------------------------------
__global__ void kA(const float* __restrict__ u, const float* __restrict__ w1) {
    const int n   = blockIdx.x >> 8;
    const int rr  = blockIdx.x & 255;
    const int tid = threadIdx.x;            // 0..127

    __shared__ float us[UD * VD];
    __shared__ float s[UD];

    const float4* ub4 = reinterpret_cast<const float4*>(u + (size_t)(n * RD + rr) * (UD * VD));
    float4* us4 = reinterpret_cast<float4*>(us);
    #pragma unroll
    for (int j = 0; j < 8; j++) us4[tid + j * 128] = ub4[tid + j * 128];
    __syncthreads();

    if (tid < UD) {
        float acc = 0.f;
        #pragma unroll 8
        for (int v = 0; v < VD; v++)
            acc += us[tid * VD + ((v + tid) & (VD - 1))];
        s[tid] = acc;
    }
    __syncthreads();

    float acc = 0.f;
    const float* w1b = w1 + (size_t)rr * UD * HD + tid;
    #pragma unroll 8
    for (int uu = 0; uu < UD; uu++)
        acc += s[uu] * w1b[uu * HD];
    g_t[(n * RD + rr) * HD + tid] = acc;
}

// ---------------------------------------------------------------------------
// Kernel B: v[tok,h] = relu( sum_r r[tok,rr] * t[n,rr,h] )
// ---------------------------------------------------------------------------
__global__ void kB(const float* __restrict__ r) {
    const int b    = blockIdx.x;
    const int tid  = threadIdx.x;           // h
    const int tok0 = b * 16;
    const int n    = tok0 >> 10;

    __shared__ float rs[16 * RD];
    const float4* rb4 = reinterpret_cast<const float4*>(r + (size_t)tok0 * RD);
    float4* rs4 = reinterpret_cast<float4*>(rs);
    #pragma unroll
    for (int j = 0; j < 8; j++) rs4[tid + j * 128] = rb4[tid + j * 128];
    __syncthreads();

    float acc[16];
    #pragma unroll
    for (int t = 0; t < 16; t++) acc[t] = 0.f;

    const float* tb = g_t + (size_t)n * RD * HD + tid;
    for (int rr = 0; rr < RD; rr += 4) {
        const float w0  = tb[(rr + 0) * HD];
        const float w1v = tb[(rr + 1) * HD];
        const float w2v = tb[(rr + 2) * HD];
        const float w3v = tb[(rr + 3) * HD];
        #pragma unroll
        for (int t = 0; t < 16; t++) {
            float4 rv = *reinterpret_cast<const float4*>(&rs[t * RD + rr]);
            acc[t] += rv.x * w0 + rv.y * w1v + rv.z * w2v + rv.w * w3v;
        }
    }
    #pragma unroll
    for (int t = 0; t < 16; t++)
        g_v[(size_t)(tok0 + t) * HD + tid] = fmaxf(acc[t], 0.f);
}

// ---------------------------------------------------------------------------
// Kernel C (dominant): out[t,vv] = sum_{x,h} (x[t,x]*v[t,h]) * w2[x,vv,h]
// mma.sync.m16n8k16.f16 (f32 accum), A generated in registers (rank-1 per x0).
// Block: 128 tokens x 64 vv; 8 warps = 4 token-groups(32 tok) x 2 vv-halves.
// Outer loop: h-half (v frags -> 64 regs). Inner: x0 with double-buffered
// 8KB pre-packed B chunks (cp.async), 1 LDS.128 feeds 4 mma, M=32 reuse.
// ---------------------------------------------------------------------------
#define XTS 132
#define KC_SMEM_DYN ((2 * 2048 + 128 * XTS) * 4)   // two 8KB B bufs + x tile

#define MMA_F16(ac, a0, a1, a2, a3, b0, b1)                                    \
    asm volatile("mma.sync.aligned.m16n8k16.row.col.f32.f16.f16.f32 "          \
        "{%0,%1,%2,%3}, {%4,%5,%6,%7}, {%8,%9}, {%0,%1,%2,%3};"                \
        : "+f"((ac)[0]), "+f"((ac)[1]), "+f"((ac)[2]), "+f"((ac)[3])           \
        : "r"(a0), "r"(a1), "r"(a2), "r"(a3), "r"(b0), "r"(b1))

__global__ __launch_bounds__(256, 1) void kC(const float* __restrict__ x) {
    extern __shared__ __align__(128) float sm[];
    float* b0s = sm;                 // 2048 floats = 8KB
    float* b1s = sm + 2048;
    float* xs  = sm + 4096;          // 128 x XTS

    const int tid    = threadIdx.x;
    const int wid    = tid >> 5;
    const int lane   = tid & 31;
    const int g      = lane >> 2;
    const int kl     = lane & 3;
    const int split  = blockIdx.x >> 6;
    const int tile   = blockIdx.x & 63;
    const int tok0   = tile * 128;
    const int xbase  = split * 128;
    const int tokgrp = wid & 3;
    const int vvhalf = wid >> 2;

    // Stage x half-tile [128 tok x 128 x]
    {
        const float4* xg = reinterpret_cast<const float4*>(x + (size_t)tok0 * XD + xbase);
        #pragma unroll
        for (int j = 0; j < 16; j++) {
            int idx = tid + j * 256;           // 0..4095 float4
            int row = idx >> 5, c4 = idx & 31;
            *reinterpret_cast<float4*>(&xs[row * XTS + c4 * 4]) = xg[row * (XD / 4) + c4];
        }
    }
    __syncthreads();

    uint32_t bsm[2];
    {
        uint64_t t0, t1;
        asm("cvta.to.shared.u64 %0, %1;" : "=l"(t0) : "l"(b0s));
        asm("cvta.to.shared.u64 %0, %1;" : "=l"(t1) : "l"(b1s));
        bsm[0] = (uint32_t)t0; bsm[1] = (uint32_t)t1;
    }
    const float* bufs[2] = { b0s, b1s };

    float acc[2][4][4];
    #pragma unroll
    for (int mt = 0; mt < 2; mt++)
        #pragma unroll
        for (int nt = 0; nt < 4; nt++)
            #pragma unroll
            for (int q = 0; q < 4; q++) acc[mt][nt][q] = 0.f;

    for (int half = 0; half < 2; half++) {
        // v fragments for this h-half: vr[mt][r][ch][klocal], 64 regs.
        float vr[2][2][4][4];
        #pragma unroll
        for (int mt = 0; mt < 2; mt++)
            #pragma unroll
            for (int rr2 = 0; rr2 < 2; rr2++) {
                int row = tok0 + tokgrp * 32 + mt * 16 + rr2 * 8 + g;
                const float* vp = g_v + (size_t)row * HD + half * 64 + kl * 2;
                #pragma unroll
                for (int ch = 0; ch < 4; ch++) {
                    float2 lo = *reinterpret_cast<const float2*>(vp + ch * 16);
                    float2 hi = *reinterpret_cast<const float2*>(vp + ch * 16 + 8);
                    vr[mt][rr2][ch][0] = lo.x; vr[mt][rr2][ch][1] = lo.y;
                    vr[mt][rr2][ch][2] = hi.x; vr[mt][rr2][ch][3] = hi.y;
                }
            }

        // B chunk loader: 8KB pre-packed fp16 for (x0, half)
        auto cpB = [&](int x0i, uint32_t dst) {
            const char* src = reinterpret_cast<const char*>(g_w2h)
                            + (size_t)(xbase + x0i) * 16384 + half * 8192;
            #pragma unroll
            for (int j = 0; j < 2; j++) {
                int id = tid + j * 256;
                asm volatile("cp.async.cg.shared.global [%0], [%1], 16;"
                             :: "r"(dst + id * 16), "l"(src + id * 16) : "memory");
            }
        };

        cpB(0, bsm[0]);
        asm volatile("cp.async.commit_group;" ::: "memory");

        for (int x0 = 0; x0 < 128; x0++) {
            if (x0 + 1 < 128) cpB(x0 + 1, bsm[(x0 + 1) & 1]);
            asm volatile("cp.async.commit_group;" ::: "memory");
            asm volatile("cp.async.wait_group 1;" ::: "memory");
            __syncthreads();

            float xa0 = xs[(tokgrp * 32 +      g) * XTS + x0];
            float xa1 = xs[(tokgrp * 32 +  8 + g) * XTS + x0];
            float xa2 = xs[(tokgrp * 32 + 16 + g) * XTS + x0];
            float xa3 = xs[(tokgrp * 32 + 24 + g) * XTS + x0];
            const uint4* Bq = reinterpret_cast<const uint4*>(bufs[x0 & 1]);

            #pragma unroll
            for (int hcp = 0; hcp < 2; hcp++) {
                // A fragments for chunks ch = 2*hcp, 2*hcp+1, both M-tiles
                uint32_t A[2][2][4];
                #pragma unroll
                for (int cc = 0; cc < 2; cc++) {
                    int ch = hcp * 2 + cc;
                    #pragma unroll
                    for (int mt = 0; mt < 2; mt++) {
                        float xl = mt ? xa2 : xa0;   // rows +0
                        float xh = mt ? xa3 : xa1;   // rows +8
                        PACK_H2(A[cc][mt][0], xl * vr[mt][0][ch][0], xl * vr[mt][0][ch][1]);
                        PACK_H2(A[cc][mt][1], xh * vr[mt][1][ch][0], xh * vr[mt][1][ch][1]);
                        PACK_H2(A[cc][mt][2], xl * vr[mt][0][ch][2], xl * vr[mt][0][ch][3]);
                        PACK_H2(A[cc][mt][3], xh * vr[mt][1][ch][2], xh * vr[mt][1][ch][3]);
                    }
                }
                #pragma unroll
                for (int nt = 0; nt < 4; nt++) {
                    uint4 Bv = Bq[hcp * 256 + (vvhalf * 32 + nt * 8 + g) * 4 + kl];
                    MMA_F16(acc[0][nt], A[0][0][0], A[0][0][1], A[0][0][2], A[0][0][3], Bv.x, Bv.y);
                    MMA_F16(acc[1][nt], A[0][1][0], A[0][1][1], A[0][1][2], A[0][1][3], Bv.x, Bv.y);
                    MMA_F16(acc[0][nt], A[1][0][0], A[1][0][1], A[1][0][2], A[1][0][3], Bv.z, Bv.w);
                    MMA_F16(acc[1][nt], A[1][1][0], A[1][1][1], A[1][1][2], A[1][1][3], Bv.z, Bv.w);
                }
            }
        }
        asm volatile("cp.async.wait_group 0;" ::: "memory");
        __syncthreads();
    }

    // Epilogue: partials (still scaled by 1024; kD rescales)
    float* pp = g_part[split];
    #pragma unroll
    for (int mt = 0; mt < 2; mt++) {
        int r0 = tok0 + tokgrp * 32 + mt * 16 + g;
        #pragma unroll
        for (int nt = 0; nt < 4; nt++) {
            int col = vvhalf * 32 + nt * 8 + kl * 2;
            *reinterpret_cast<float2*>(&pp[(size_t)r0 * VD + col]) =
                make_float2(acc[mt][nt][0], acc[mt][nt][1]);
            *reinterpret_cast<float2*>(&pp[(size_t)(r0 + 8) * VD + col]) =
                make_float2(acc[mt][nt][2], acc[mt][nt][3]);
        }
    }
}

// ---------------------------------------------------------------------------
// Kernel D: out = (part0 + part1) * 2^-10  (undo exact w2 prescale)
// ---------------------------------------------------------------------------
__global__ void kD(float* __restrict__ out) {
    const float S = 1.0f / 1024.0f;
    int i = blockIdx.x * 256 + threadIdx.x;   // float4 index
    float4 a = reinterpret_cast<const float4*>(g_part[0])[i];
    float4 b = reinterpret_cast<const float4*>(g_part[1])[i];
    float4 o;
    o.x = (a.x + b.x) * S; o.y = (a.y + b.y) * S;
    o.z = (a.z + b.z) * S; o.w = (a.w + b.w) * S;
    reinterpret_cast<float4*>(out)[i] = o;
}

// ---------------------------------------------------------------------------
extern "C" void kernel_launch(void* const* d_in, const int* in_sizes, int n_in,
                              void* d_out, int out_size) {
    const float* x  = (const float*)d_in[0];
    const float* r  = (const float*)d_in[1];
    const float* u  = (const float*)d_in[2];
    const float* w1 = (const float*)d_in[3];
    const float* w2 = (const float*)d_in[4];
    float* out = (float*)d_out;

    cudaFuncSetAttribute(kC, cudaFuncAttributeMaxDynamicSharedMemorySize, KC_SMEM_DYN);

    kW<<<(XD * VD * HD) / 1024, 256>>>(w2);
    kA<<<NB * RD, 128>>>(u, w1);
    kB<<<NTOK / 16, 128>>>(r);
    kC<<<128, 256, KC_SMEM_DYN>>>(x);
    kD<<<(NTOK * VD) / 1024, 256>>>(out);
}

// round 7
// speedup vs baseline: 1.8125x; 1.3002x over previous
#include <cuda_runtime.h>
#include <cuda_fp16.h>
#include <cstdint>

// Shapes
#define NB   8
#define NTOK 8192      // N * I * J
#define XD   256
#define RD   256
#define UD   64
#define VD   64
#define HD   128

// Scratch (allocation-free: __device__ globals)
__device__ float  g_t[NB * RD * HD];         // t[n,r,h]
__device__ __half g_vh[NTOK * HD];           // v[tok,h] in fp16 (written by kB)
__device__ __half g_w2h[XD * VD * HD];       // fragment-packed fp16 w2 * 1024 (4MB)
__device__ float  g_part[2][NTOK * VD];      // K-split partial sums (scaled by 1024)

// ---------------------------------------------------------------------------
// Kernel W: fragment-pack w2 for kC (fp16, scaled by 2^10 exact).
// Consumer (g=lane>>2, kl=lane&3) at (x0, hcp, nt) does one LDS.128 = 8 fp16:
//   slot = codd*4 + breg*2 + dlt, ch = hcp*2 + codd, k-in-chunk = breg*8+kl*2+dlt
// Byte addr = x0*16384 + hcp*4096 + vv*64 + kl*16 + slot*2.
// ---------------------------------------------------------------------------
__global__ void kW(const float* __restrict__ w2) {
    int idx = blockIdx.x * 256 + threadIdx.x;      // float4 over w2, h fastest
    float4 v = reinterpret_cast<const float4*>(w2)[idx];
    float e[4] = { v.x, v.y, v.z, v.w };
    int h0 = (idx << 2) & (HD - 1);
    int vv = (idx >> 5) & (VD - 1);
    int x0 = idx >> 11;
    char* base = reinterpret_cast<char*>(g_w2h);
    #pragma unroll
    for (int q = 0; q < 4; q++) {
        int h    = h0 + q;
        int ch   = h >> 4, kk = h & 15;
        int breg = kk >> 3, kk2 = kk & 7;
        int kl   = kk2 >> 1, dlt = kk2 & 1;
        int hcp  = ch >> 1, codd = ch & 1;
        int slot = codd * 4 + breg * 2 + dlt;
        size_t off = (size_t)x0 * 16384 + hcp * 4096 + vv * 64 + kl * 16 + slot * 2;
        *reinterpret_cast<__half*>(base + off) = __float2half_rn(e[q] * 1024.0f);
    }
}

// ---------------------------------------------------------------------------
// Kernel A: t[n,r,h] = sum_u ( sum_v u[n,r,u,v] ) * w1[r,u,h]
// ---------------------------------------------------------------------------
__global__ void kA(const float* __restrict__ u, const float* __restrict__ w1) {
    const int n   = blockIdx.x >> 8;
    const int rr  = blockIdx.x & 255;
    const int tid = threadIdx.x;            // 0..127

    __shared__ float us[UD * VD];
    __shared__ float s[UD];

    const float4* ub4 = reinterpret_cast<const float4*>(u + (size_t)(n * RD + rr) * (UD * VD));
    float4* us4 = reinterpret_cast<float4*>(us);
    #pragma unroll
    for (int j = 0; j < 8; j++) us4[tid + j * 128] = ub4[tid + j * 128];
    __syncthreads();

    if (tid < UD) {
        float acc = 0.f;
        #pragma unroll 8
        for (int v = 0; v < VD; v++)
            acc += us[tid * VD + ((v + tid) & (VD - 1))];
        s[tid] = acc;
    }
    __syncthreads();

    float acc = 0.f;
    const float* w1b = w1 + (size_t)rr * UD * HD + tid;
    #pragma unroll 8
    for (int uu = 0; uu < UD; uu++)
        acc += s[uu] * w1b[uu * HD];
    g_t[(n * RD + rr) * HD + tid] = acc;
}

// ---------------------------------------------------------------------------
// Kernel B: v[tok,h] = relu( sum_r r[tok,rr] * t[n,rr,h] )  -> fp16
// ---------------------------------------------------------------------------
__global__ void kB(const float* __restrict__ r) {
    const int b    = blockIdx.x;
    const int tid  = threadIdx.x;           // h
    const int tok0 = b * 16;
    const int n    = tok0 >> 10;

    __shared__ float rs[16 * RD];
    const float4* rb4 = reinterpret_cast<const float4*>(r + (size_t)tok0 * RD);
    float4* rs4 = reinterpret_cast<float4*>(rs);
    #pragma unroll
    for (int j = 0; j < 8; j++) rs4[tid + j * 128] = rb4[tid + j * 128];
    __syncthreads();

    float acc[16];
    #pragma unroll
    for (int t = 0; t < 16; t++) acc[t] = 0.f;

    const float* tb = g_t + (size_t)n * RD * HD + tid;
    for (int rr = 0; rr < RD; rr += 4) {
        const float w0  = tb[(rr + 0) * HD];
        const float w1v = tb[(rr + 1) * HD];
        const float w2v = tb[(rr + 2) * HD];
        const float w3v = tb[(rr + 3) * HD];
        #pragma unroll
        for (int t = 0; t < 16; t++) {
            float4 rv = *reinterpret_cast<const float4*>(&rs[t * RD + rr]);
            acc[t] += rv.x * w0 + rv.y * w1v + rv.z * w2v + rv.w * w3v;
        }
    }
    #pragma unroll
    for (int t = 0; t < 16; t++)
        g_vh[(size_t)(tok0 + t) * HD + tid] = __float2half_rn(fmaxf(acc[t], 0.f));
}

// ---------------------------------------------------------------------------
// Kernel C (dominant): out[t,vv] = sum_{x,h} (x[t,x]*v[t,h]) * w2[x,vv,h]
// mma.sync.m16n8k16.f16 (f32 accum). A generated per x0 as HMUL2(x-splat, v).
// 512 threads = 16 warps: 4 token-groups (32 tok) x 4 vv-quarters (16 vv).
// All 128 h of v held in 64 packed regs; 128 stages (one x0 = 16KB B chunk),
// 4-deep cp.async pipeline, one barrier per stage.
// ---------------------------------------------------------------------------
#define XTS  132
#define NBUF 4
#define KC_SMEM_DYN ((NBUF * 4096 + 128 * XTS) * 4)   // 64KB bufs + x tile

#define HMUL2(d, a, b) \
    asm("mul.rn.f16x2 %0, %1, %2;" : "=r"(d) : "r"(a), "r"(b))
#define SPLAT_H2(d, f) \
    asm("cvt.rn.f16x2.f32 %0, %1, %1;" : "=r"(d) : "f"(f))
#define MMA_F16(ac, a0, a1, a2, a3, b0, b1)                                    \
    asm volatile("mma.sync.aligned.m16n8k16.row.col.f32.f16.f16.f32 "          \
        "{%0,%1,%2,%3}, {%4,%5,%6,%7}, {%8,%9}, {%0,%1,%2,%3};"                \
        : "+f"((ac)[0]), "+f"((ac)[1]), "+f"((ac)[2]), "+f"((ac)[3])           \
        : "r"(a0), "r"(a1), "r"(a2), "r"(a3), "r"(b0), "r"(b1))

__global__ __launch_bounds__(512, 1) void kC(const float* __restrict__ x) {
    extern __shared__ __align__(128) float sm[];
    float* bufs = sm;                    // NBUF x 4096 floats (16KB each)
    float* xs   = sm + NBUF * 4096;      // 128 x XTS

    const int tid    = threadIdx.x;
    const int wid    = tid >> 5;
    const int lane   = tid & 31;
    const int g      = lane >> 2;
    const int kl     = lane & 3;
    const int split  = blockIdx.x >> 6;
    const int tile   = blockIdx.x & 63;
    const int tok0   = tile * 128;
    const int xbase  = split * 128;
    const int tokgrp = wid & 3;
    const int vvq    = wid >> 2;

    uint32_t bsm;
    {
        uint64_t t0;
        asm("cvta.to.shared.u64 %0, %1;" : "=l"(t0) : "l"(bufs));
        bsm = (uint32_t)t0;
    }

    // B chunk loader: 16KB pre-packed fp16 for x0 -> buf[x0 & 3]
    auto cpB = [&](int x0i) {
        uint32_t dst = bsm + (uint32_t)(x0i & 3) * 16384u;
        const char* src = reinterpret_cast<const char*>(g_w2h)
                        + (size_t)(xbase + x0i) * 16384;
        #pragma unroll
        for (int j = 0; j < 2; j++) {
            int id = tid + j * 512;
            asm volatile("cp.async.cg.shared.global [%0], [%1], 16;"
                         :: "r"(dst + id * 16), "l"(src + id * 16) : "memory");
        }
        asm volatile("cp.async.commit_group;" ::: "memory");
    };

    // Prefetch 3 stages immediately (hide behind x staging + vr loads)
    cpB(0); cpB(1); cpB(2);

    // Stage x half-tile [128 tok x 128 x] (fp32, padded rows)
    {
        const float4* xg = reinterpret_cast<const float4*>(x + (size_t)tok0 * XD + xbase);
        #pragma unroll
        for (int j = 0; j < 8; j++) {
            int idx = tid + j * 512;           // 0..4095 float4
            int row = idx >> 5, c4 = idx & 31;
            *reinterpret_cast<float4*>(&xs[row * XTS + c4 * 4]) = xg[row * (XD / 4) + c4];
        }
    }

    // v fragments (fp16-packed, all 128 h): vrl/vrh[mt][rr2][ch]
    uint32_t vrl[2][2][8], vrh[2][2][8];
    #pragma unroll
    for (int mt = 0; mt < 2; mt++)
        #pragma unroll
        for (int rr2 = 0; rr2 < 2; rr2++) {
            int row = tok0 + tokgrp * 32 + mt * 16 + rr2 * 8 + g;
            const uint32_t* vp = reinterpret_cast<const uint32_t*>(
                g_vh + (size_t)row * HD);
            #pragma unroll
            for (int ch = 0; ch < 8; ch++) {
                vrl[mt][rr2][ch] = vp[ch * 8 + kl];       // h = ch*16 + kl*2, +1
                vrh[mt][rr2][ch] = vp[ch * 8 + kl + 4];   // h = ch*16 + kl*2+8, +9
            }
        }
    __syncthreads();

    float acc[2][2][4];
    #pragma unroll
    for (int mt = 0; mt < 2; mt++)
        #pragma unroll
        for (int nt = 0; nt < 2; nt++)
            #pragma unroll
            for (int q = 0; q < 4; q++) acc[mt][nt][q] = 0.f;

    for (int x0 = 0; x0 < 128; x0++) {
        asm volatile("cp.async.wait_group 2;" ::: "memory");
        __syncthreads();
        if (x0 + 3 < 128) cpB(x0 + 3);
        else asm volatile("cp.async.commit_group;" ::: "memory");  // keep accounting

        // x splats for this x0 (4 rows per warp, broadcast across kl)
        uint32_t xp[2][2];
        #pragma unroll
        for (int mt = 0; mt < 2; mt++)
            #pragma unroll
            for (int rr2 = 0; rr2 < 2; rr2++) {
                float xv = xs[(tokgrp * 32 + mt * 16 + rr2 * 8 + g) * XTS + x0];
                SPLAT_H2(xp[mt][rr2], xv);
            }

        const uint4* Bq = reinterpret_cast<const uint4*>(bufs + (x0 & 3) * 4096);

        #pragma unroll
        for (int hcp = 0; hcp < 4; hcp++) {
            uint32_t A[2][2][4];                 // [cc][mt][reg]
            #pragma unroll
            for (int cc = 0; cc < 2; cc++) {
                int ch = hcp * 2 + cc;
                #pragma unroll
                for (int mt = 0; mt < 2; mt++) {
                    HMUL2(A[cc][mt][0], xp[mt][0], vrl[mt][0][ch]);
                    HMUL2(A[cc][mt][1], xp[mt][1], vrl[mt][1][ch]);
                    HMUL2(A[cc][mt][2], xp[mt][0], vrh[mt][0][ch]);
                    HMUL2(A[cc][mt][3], xp[mt][1], vrh[mt][1][ch]);
                }
            }
            #pragma unroll
            for (int nt = 0; nt < 2; nt++) {
                uint4 Bv = Bq[hcp * 256 + (vvq * 16 + nt * 8 + g) * 4 + kl];
                MMA_F16(acc[0][nt], A[0][0][0], A[0][0][1], A[0][0][2], A[0][0][3], Bv.x, Bv.y);
                MMA_F16(acc[1][nt], A[0][1][0], A[0][1][1], A[0][1][2], A[0][1][3], Bv.x, Bv.y);
                MMA_F16(acc[0][nt], A[1][0][0], A[1][0][1], A[1][0][2], A[1][0][3], Bv.z, Bv.w);
                MMA_F16(acc[1][nt], A[1][1][0], A[1][1][1], A[1][1][2], A[1][1][3], Bv.z, Bv.w);
            }
        }
    }

    // Epilogue: partials (still scaled by 1024; kD rescales)
    float* pp = g_part[split];
    #pragma unroll
    for (int mt = 0; mt < 2; mt++) {
        int r0 = tok0 + tokgrp * 32 + mt * 16 + g;
        #pragma unroll
        for (int nt = 0; nt < 2; nt++) {
            int col = vvq * 16 + nt * 8 + kl * 2;
            *reinterpret_cast<float2*>(&pp[(size_t)r0 * VD + col]) =
                make_float2(acc[mt][nt][0], acc[mt][nt][1]);
            *reinterpret_cast<float2*>(&pp[(size_t)(r0 + 8) * VD + col]) =
                make_float2(acc[mt][nt][2], acc[mt][nt][3]);
        }
    }
}

// ---------------------------------------------------------------------------
// Kernel D: out = (part0 + part1) * 2^-10  (undo exact w2 prescale)
// ---------------------------------------------------------------------------
__global__ void kD(float* __restrict__ out) {
    const float S = 1.0f / 1024.0f;
    int i = blockIdx.x * 256 + threadIdx.x;   // float4 index
    float4 a = reinterpret_cast<const float4*>(g_part[0])[i];
    float4 b = reinterpret_cast<const float4*>(g_part[1])[i];
    float4 o;
    o.x = (a.x + b.x) * S; o.y = (a.y + b.y) * S;
    o.z = (a.z + b.z) * S; o.w = (a.w + b.w) * S;
    reinterpret_cast<float4*>(out)[i] = o;
}

// ---------------------------------------------------------------------------
extern "C" void kernel_launch(void* const* d_in, const int* in_sizes, int n_in,
                              void* d_out, int out_size) {
    const float* x  = (const float*)d_in[0];
    const float* r  = (const float*)d_in[1];
    const float* u  = (const float*)d_in[2];
    const float* w1 = (const float*)d_in[3];
    const float* w2 = (const float*)d_in[4];
    float* out = (float*)d_out;

    cudaFuncSetAttribute(kC, cudaFuncAttributeMaxDynamicSharedMemorySize, KC_SMEM_DYN);

    kW<<<(XD * VD * HD) / 1024, 256>>>(w2);
    kA<<<NB * RD, 128>>>(u, w1);
    kB<<<NTOK / 16, 128>>>(r);
    kC<<<128, 512, KC_SMEM_DYN>>>(x);
    kD<<<(NTOK * VD) / 1024, 256>>>(out);
}

// round 9
// speedup vs baseline: 1.8831x; 1.0390x over previous
#include <cuda_runtime.h>
#include <cuda_fp16.h>
#include <cstdint>

// Shapes
#define NB   8
#define NTOK 8192      // N * I * J
#define XD   256
#define RD   256
#define UD   64
#define VD   64
#define HD   128

// Scratch (allocation-free: __device__ globals)
__device__ float  g_t[NB * RD * HD];         // t[n,r,h]
__device__ __half g_vh[NTOK * HD];           // v[tok,h] in fp16 (written by kB)
__device__ __half g_w2h[XD * VD * HD];       // fragment-packed fp16 w2 * 1024 (4MB)
__device__ float  g_part[2][NTOK * VD];      // K-split partial sums (scaled by 1024)

// ---------------------------------------------------------------------------
// Kernel W: fragment-pack w2 for kC (fp16, scaled by 2^10 exact).
// Consumer (g=lane>>2, kl=lane&3) at (x0, hcp, nt) does one LDS.128 = 8 fp16:
//   slot = codd*4 + breg*2 + dlt, ch = hcp*2 + codd, k-in-chunk = breg*8+kl*2+dlt
// Byte addr = x0*16384 + hcp*4096 + vv*64 + kl*16 + slot*2.
// ---------------------------------------------------------------------------
__global__ void kW(const float* __restrict__ w2) {
    int idx = blockIdx.x * 256 + threadIdx.x;      // float4 over w2, h fastest
    float4 v = reinterpret_cast<const float4*>(w2)[idx];
    float e[4] = { v.x, v.y, v.z, v.w };
    int h0 = (idx << 2) & (HD - 1);
    int vv = (idx >> 5) & (VD - 1);
    int x0 = idx >> 11;
    char* base = reinterpret_cast<char*>(g_w2h);
    #pragma unroll
    for (int q = 0; q < 4; q++) {
        int h    = h0 + q;
        int ch   = h >> 4, kk = h & 15;
        int breg = kk >> 3, kk2 = kk & 7;
        int kl   = kk2 >> 1, dlt = kk2 & 1;
        int hcp  = ch >> 1, codd = ch & 1;
        int slot = codd * 4 + breg * 2 + dlt;
        size_t off = (size_t)x0 * 16384 + hcp * 4096 + vv * 64 + kl * 16 + slot * 2;
        *reinterpret_cast<__half*>(base + off) = __float2half_rn(e[q] * 1024.0f);
    }
}

// ---------------------------------------------------------------------------
// Kernel A: t[n,r,h] = sum_u ( sum_v u[n,r,u,v] ) * w1[r,u,h]
// 256 threads. Phase 1: (u, quarter) per thread + 4-lane shuffle reduce.
// Phase 2: h per thread (tid<128), 4 independent accumulators.
// ---------------------------------------------------------------------------
#define UAS 68   // padded row stride for u staging (kills 4-way conflicts)
__global__ void kA(const float* __restrict__ u, const float* __restrict__ w1) {
    const int n   = blockIdx.x >> 8;
    const int rr  = blockIdx.x & 255;
    const int tid = threadIdx.x;            // 0..255

    __shared__ float us[UD * UAS];
    __shared__ float s[UD];

    // u tile = 64x64 floats = 1024 float4s -> 4 iterations of 256 threads
    const float4* ub4 = reinterpret_cast<const float4*>(u + (size_t)(n * RD + rr) * (UD * VD));
    #pragma unroll
    for (int j = 0; j < 4; j++) {
        int idx = tid + j * 256;            // float4 index, 0..1023
        int row = idx >> 4, col = idx & 15;
        *reinterpret_cast<float4*>(&us[row * UAS + col * 4]) = ub4[idx];
    }
    __syncthreads();

    {   // Phase 1: sum over v (64) -> s[u]
        int uu = tid >> 2, part = tid & 3;
        const float4* p4 = reinterpret_cast<const float4*>(&us[uu * UAS + part * 16]);
        float4 a = p4[0], b = p4[1], c = p4[2], d = p4[3];
        float sum = ((a.x + a.y) + (a.z + a.w)) + ((b.x + b.y) + (b.z + b.w))
                  + ((c.x + c.y) + (c.z + c.w)) + ((d.x + d.y) + (d.z + d.w));
        sum += __shfl_xor_sync(0xffffffffu, sum, 1);
        sum += __shfl_xor_sync(0xffffffffu, sum, 2);
        if (part == 0) s[uu] = sum;
    }
    __syncthreads();

    if (tid < HD) {   // Phase 2: t[h] = sum_u s[u] * w1[r,u,h]
        float a0 = 0.f, a1 = 0.f, a2 = 0.f, a3 = 0.f;
        const float* w1b = w1 + (size_t)rr * UD * HD + tid;
        #pragma unroll 4
        for (int uu = 0; uu < UD; uu += 4) {
            a0 += s[uu + 0] * w1b[(uu + 0) * HD];
            a1 += s[uu + 1] * w1b[(uu + 1) * HD];
            a2 += s[uu + 2] * w1b[(uu + 2) * HD];
            a3 += s[uu + 3] * w1b[(uu + 3) * HD];
        }
        g_t[(n * RD + rr) * HD + tid] = (a0 + a1) + (a2 + a3);
    }
}

// ---------------------------------------------------------------------------
// Kernel B: v[tok,h] = relu( sum_r r[tok,rr] * t[n,rr,h] )  -> fp16
// ---------------------------------------------------------------------------
__global__ void kB(const float* __restrict__ r) {
    const int b    = blockIdx.x;
    const int tid  = threadIdx.x;           // h
    const int tok0 = b * 16;
    const int n    = tok0 >> 10;

    __shared__ float rs[16 * RD];
    const float4* rb4 = reinterpret_cast<const float4*>(r + (size_t)tok0 * RD);
    float4* rs4 = reinterpret_cast<float4*>(rs);
    #pragma unroll
    for (int j = 0; j < 8; j++) rs4[tid + j * 128] = rb4[tid + j * 128];
    __syncthreads();

    float acc[16];
    #pragma unroll
    for (int t = 0; t < 16; t++) acc[t] = 0.f;

    const float* tb = g_t + (size_t)n * RD * HD + tid;
    for (int rr = 0; rr < RD; rr += 4) {
        const float w0  = tb[(rr + 0) * HD];
        const float w1v = tb[(rr + 1) * HD];
        const float w2v = tb[(rr + 2) * HD];
        const float w3v = tb[(rr + 3) * HD];
        #pragma unroll
        for (int t = 0; t < 16; t++) {
            float4 rv = *reinterpret_cast<const float4*>(&rs[t * RD + rr]);
            acc[t] += rv.x * w0 + rv.y * w1v + rv.z * w2v + rv.w * w3v;
        }
    }
    #pragma unroll
    for (int t = 0; t < 16; t++)
        g_vh[(size_t)(tok0 + t) * HD + tid] = __float2half_rn(fmaxf(acc[t], 0.f));
}

// ---------------------------------------------------------------------------
// Kernel C (dominant): out[t,vv] = sum_{x,h} (x[t,x]*v[t,h]) * w2[x,vv,h]
// mma.sync.m16n8k16.f16 (f32 accum). A generated per x0 as HMUL2(x-splat, v).
// 512 threads = 16 warps: 8 token-groups (16 tok) x 2 vv-halves (32 vv).
// Pair-stages: one barrier per 2 x0 (64 iterations), 3 pair-buffers (96KB),
// cp.async prefetch distance 2.
// ---------------------------------------------------------------------------
#define XTS  132
#define KC_SMEM_DYN ((6 * 4096 + 128 * XTS) * 4)   // 96KB B bufs + 66KB x tile

#define HMUL2(d, a, b) \
    asm("mul.rn.f16x2 %0, %1, %2;" : "=r"(d) : "r"(a), "r"(b))
#define SPLAT_H2(d, f) \
    asm("cvt.rn.f16x2.f32 %0, %1, %1;" : "=r"(d) : "f"(f))
#define MMA_F16(ac, a0, a1, a2, a3, b0, b1)                                    \
    asm volatile("mma.sync.aligned.m16n8k16.row.col.f32.f16.f16.f32 "          \
        "{%0,%1,%2,%3}, {%4,%5,%6,%7}, {%8,%9}, {%0,%1,%2,%3};"                \
        : "+f"((ac)[0]), "+f"((ac)[1]), "+f"((ac)[2]), "+f"((ac)[3])           \
        : "r"(a0), "r"(a1), "r"(a2), "r"(a3), "r"(b0), "r"(b1))

__global__ __launch_bounds__(512, 1) void kC(const float* __restrict__ x) {
    extern __shared__ __align__(128) float sm[];
    float* bufs = sm;                    // 6 chunks x 4096 floats (16KB each)
    float* xs   = sm + 6 * 4096;         // 128 x XTS

    const int tid    = threadIdx.x;
    const int wid    = tid >> 5;
    const int lane   = tid & 31;
    const int g      = lane >> 2;
    const int kl     = lane & 3;
    const int split  = blockIdx.x >> 6;
    const int tile   = blockIdx.x & 63;
    const int tok0   = tile * 128;
    const int xbase  = split * 128;
    const int tokgrp = wid >> 1;          // 0..7 : 16-token group
    const int vvhalf = wid & 1;           // 0/1 : 32-vv half

    uint32_t bsm;
    {
        uint64_t t0;
        asm("cvta.to.shared.u64 %0, %1;" : "=l"(t0) : "l"(bufs));
        bsm = (uint32_t)t0;
    }

    // Pair loader: 32KB (x0 = 2p, 2p+1) -> pair-slot p%3, one commit group.
    auto cpPair = [&](int p) {
        uint32_t dst = bsm + (uint32_t)(p % 3) * 32768u;
        const char* src = reinterpret_cast<const char*>(g_w2h)
                        + (size_t)(xbase + 2 * p) * 16384;
        #pragma unroll
        for (int j = 0; j < 4; j++) {
            int id = tid + j * 512;
            asm volatile("cp.async.cg.shared.global [%0], [%1], 16;"
                         :: "r"(dst + id * 16), "l"(src + id * 16) : "memory");
        }
        asm volatile("cp.async.commit_group;" ::: "memory");
    };

    cpPair(0); cpPair(1);

    // Stage x half-tile [128 tok x 128 x] (fp32, padded rows)
    {
        const float4* xg = reinterpret_cast<const float4*>(x + (size_t)tok0 * XD + xbase);
        #pragma unroll
        for (int j = 0; j < 8; j++) {
            int idx = tid + j * 512;           // 0..4095 float4
            int row = idx >> 5, c4 = idx & 31;
            *reinterpret_cast<float4*>(&xs[row * XTS + c4 * 4]) = xg[row * (XD / 4) + c4];
        }
    }

    // v fragments (fp16-packed, all 128 h): vrl/vrh[rr2][ch], 32 regs
    uint32_t vrl[2][8], vrh[2][8];
    #pragma unroll
    for (int rr2 = 0; rr2 < 2; rr2++) {
        int row = tok0 + tokgrp * 16 + rr2 * 8 + g;
        const uint32_t* vp = reinterpret_cast<const uint32_t*>(g_vh + (size_t)row * HD);
        #pragma unroll
        for (int ch = 0; ch < 8; ch++) {
            vrl[rr2][ch] = vp[ch * 8 + kl];       // h = ch*16 + kl*2, +1
            vrh[rr2][ch] = vp[ch * 8 + kl + 4];   // h = ch*16 + kl*2+8, +9
        }
    }

    float acc[4][4];
    #pragma unroll
    for (int nt = 0; nt < 4; nt++)
        #pragma unroll
        for (int q = 0; q < 4; q++) acc[nt][q] = 0.f;

    const int xrow0 = (tokgrp * 16 + g) * XTS;
    const int xrow1 = (tokgrp * 16 + 8 + g) * XTS;

    for (int p = 0; p < 64; p++) {
        asm volatile("cp.async.wait_group 1;" ::: "memory");
        __syncthreads();
        if (p + 2 < 64) cpPair(p + 2);
        else asm volatile("cp.async.commit_group;" ::: "memory");  // keep accounting

        const float* pairbase = bufs + (p % 3) * 8192;
        #pragma unroll
        for (int sub = 0; sub < 2; sub++) {
            const int x0 = 2 * p + sub;
            const uint4* Bq = reinterpret_cast<const uint4*>(pairbase + sub * 4096);
            uint32_t xp0, xp1;
            SPLAT_H2(xp0, xs[xrow0 + x0]);
            SPLAT_H2(xp1, xs[xrow1 + x0]);

            #pragma unroll
            for (int hcp = 0; hcp < 4; hcp++) {
                uint32_t A[2][4];                 // [cc][reg]
                #pragma unroll
                for (int cc = 0; cc < 2; cc++) {
                    int ch = hcp * 2 + cc;
                    HMUL2(A[cc][0], xp0, vrl[0][ch]);
                    HMUL2(A[cc][1], xp1, vrl[1][ch]);
                    HMUL2(A[cc][2], xp0, vrh[0][ch]);
                    HMUL2(A[cc][3], xp1, vrh[1][ch]);
                }
                #pragma unroll
                for (int nt = 0; nt < 4; nt++) {
                    uint4 Bv = Bq[hcp * 256 + (vvhalf * 32 + nt * 8 + g) * 4 + kl];
                    MMA_F16(acc[nt], A[0][0], A[0][1], A[0][2], A[0][3], Bv.x, Bv.y);
                    MMA_F16(acc[nt], A[1][0], A[1][1], A[1][2], A[1][3], Bv.z, Bv.w);
                }
            }
        }
    }

    // Epilogue: partials (still scaled by 1024; kD rescales)
    float* pp = g_part[split];
    {
        int r0 = tok0 + tokgrp * 16 + g;
        #pragma unroll
        for (int nt = 0; nt < 4; nt++) {
            int col = vvhalf * 32 + nt * 8 + kl * 2;
            *reinterpret_cast<float2*>(&pp[(size_t)r0 * VD + col]) =
                make_float2(acc[nt][0], acc[nt][1]);
            *reinterpret_cast<float2*>(&pp[(size_t)(r0 + 8) * VD + col]) =
                make_float2(acc[nt][2], acc[nt][3]);
        }
    }
}

// ---------------------------------------------------------------------------
// Kernel D: out = (part0 + part1) * 2^-10  (undo exact w2 prescale)
// ---------------------------------------------------------------------------
__global__ void kD(float* __restrict__ out) {
    const float S = 1.0f / 1024.0f;
    int i = blockIdx.x * 256 + threadIdx.x;   // float4 index
    float4 a = reinterpret_cast<const float4*>(g_part[0])[i];
    float4 b = reinterpret_cast<const float4*>(g_part[1])[i];
    float4 o;
    o.x = (a.x + b.x) * S; o.y = (a.y + b.y) * S;
    o.z = (a.z + b.z) * S; o.w = (a.w + b.w) * S;
    reinterpret_cast<float4*>(out)[i] = o;
}

// ---------------------------------------------------------------------------
extern "C" void kernel_launch(void* const* d_in, const int* in_sizes, int n_in,
                              void* d_out, int out_size) {
    const float* x  = (const float*)d_in[0];
    const float* r  = (const float*)d_in[1];
    const float* u  = (const float*)d_in[2];
    const float* w1 = (const float*)d_in[3];
    const float* w2 = (const float*)d_in[4];
    float* out = (float*)d_out;

    cudaFuncSetAttribute(kC, cudaFuncAttributeMaxDynamicSharedMemorySize, KC_SMEM_DYN);

    kW<<<(XD * VD * HD) / 1024, 256>>>(w2);
    kA<<<NB * RD, 256>>>(u, w1);
    kB<<<NTOK / 16, 128>>>(r);
    kC<<<128, 512, KC_SMEM_DYN>>>(x);
    kD<<<(NTOK * VD) / 1024, 256>>>(out);
}

// round 11
// speedup vs baseline: 1.9032x; 1.0107x over previous
#include <cuda_runtime.h>
#include <cuda_fp16.h>
#include <cstdint>

// Shapes
#define NB   8
#define NTOK 8192      // N * I * J
#define XD   256
#define RD   256
#define UD   64
#define VD   64
#define HD   128

// Scratch (allocation-free: __device__ globals)
__device__ float  g_t[NB * RD * HD];         // t[n,r,h]
__device__ __half g_vh[NTOK * HD];           // v[tok,h] in fp16 (written by kB)
__device__ __half g_w2h[XD * VD * HD];       // fragment-packed fp16 w2 * 1024 (4MB)
__device__ float  g_part[2][NTOK * VD];      // K-split partial sums (scaled by 1024)

#define PACKS_H2(d, lo, hi) /* scaled pack: d = {lo,hi}*1024 as fp16x2 */      \
    asm("cvt.rn.f16x2.f32 %0, %1, %2;" : "=r"(d) : "f"((hi) * 1024.0f), "f"((lo) * 1024.0f))

// ---------------------------------------------------------------------------
// Kernel W: fragment-pack w2 for kC (fp16, scaled by 2^10 exact).
// One thread = one (x0, vv, hcp, kl) -> builds 8 halves (slots 0..7), one
// coalesced STG.128. Layout (bytes): x0*16384 + hcp*4096 + vv*64 + kl*16,
// slot = codd*4 + breg*2 + dlt, h = hcp*32 + codd*16 + breg*8 + kl*2 + dlt.
// ---------------------------------------------------------------------------
__global__ void kW(const float* __restrict__ w2) {
    int gid = blockIdx.x * 256 + threadIdx.x;     // 0 .. 262143
    int kl  = gid & 3;
    int hcp = (gid >> 2) & 3;
    int vv  = (gid >> 4) & 63;
    int x0  = gid >> 10;

    const float* src = w2 + (size_t)x0 * (VD * HD) + (size_t)vv * HD;
    uint4 o;
    {
        int hb = hcp * 32 + kl * 2;
        float2 a = *reinterpret_cast<const float2*>(src + hb);           // codd0 breg0
        float2 b = *reinterpret_cast<const float2*>(src + hb + 8);       // codd0 breg1
        float2 c = *reinterpret_cast<const float2*>(src + hb + 16);      // codd1 breg0
        float2 d = *reinterpret_cast<const float2*>(src + hb + 24);      // codd1 breg1
        PACKS_H2(o.x, a.x, a.y);
        PACKS_H2(o.y, b.x, b.y);
        PACKS_H2(o.z, c.x, c.y);
        PACKS_H2(o.w, d.x, d.y);
    }
    char* dst = reinterpret_cast<char*>(g_w2h)
              + (size_t)x0 * 16384 + hcp * 4096 + vv * 64 + kl * 16;
    *reinterpret_cast<uint4*>(dst) = o;
}

// ---------------------------------------------------------------------------
// Kernel A: t[n,r,h] = sum_u ( sum_v u[n,r,u,v] ) * w1[r,u,h]
// ---------------------------------------------------------------------------
#define UAS 68   // padded row stride for u staging
__global__ void kA(const float* __restrict__ u, const float* __restrict__ w1) {
    const int n   = blockIdx.x >> 8;
    const int rr  = blockIdx.x & 255;
    const int tid = threadIdx.x;            // 0..255

    __shared__ float us[UD * UAS];
    __shared__ float s[UD];

    const float4* ub4 = reinterpret_cast<const float4*>(u + (size_t)(n * RD + rr) * (UD * VD));
    #pragma unroll
    for (int j = 0; j < 4; j++) {
        int idx = tid + j * 256;            // float4 index, 0..1023
        int row = idx >> 4, col = idx & 15;
        *reinterpret_cast<float4*>(&us[row * UAS + col * 4]) = ub4[idx];
    }
    __syncthreads();

    {   // Phase 1: sum over v (64) -> s[u]
        int uu = tid >> 2, part = tid & 3;
        const float4* p4 = reinterpret_cast<const float4*>(&us[uu * UAS + part * 16]);
        float4 a = p4[0], b = p4[1], c = p4[2], d = p4[3];
        float sum = ((a.x + a.y) + (a.z + a.w)) + ((b.x + b.y) + (b.z + b.w))
                  + ((c.x + c.y) + (c.z + c.w)) + ((d.x + d.y) + (d.z + d.w));
        sum += __shfl_xor_sync(0xffffffffu, sum, 1);
        sum += __shfl_xor_sync(0xffffffffu, sum, 2);
        if (part == 0) s[uu] = sum;
    }
    __syncthreads();

    if (tid < HD) {   // Phase 2: t[h] = sum_u s[u] * w1[r,u,h]
        float a0 = 0.f, a1 = 0.f, a2 = 0.f, a3 = 0.f;
        const float* w1b = w1 + (size_t)rr * UD * HD + tid;
        #pragma unroll 4
        for (int uu = 0; uu < UD; uu += 4) {
            a0 += s[uu + 0] * w1b[(uu + 0) * HD];
            a1 += s[uu + 1] * w1b[(uu + 1) * HD];
            a2 += s[uu + 2] * w1b[(uu + 2) * HD];
            a3 += s[uu + 3] * w1b[(uu + 3) * HD];
        }
        g_t[(n * RD + rr) * HD + tid] = (a0 + a1) + (a2 + a3);
    }
}

// ---------------------------------------------------------------------------
// Kernel B: v[tok,h] = relu( sum_r r[tok,rr] * t[n,rr,h] )  -> fp16
// ---------------------------------------------------------------------------
__global__ void kB(const float* __restrict__ r) {
    const int b    = blockIdx.x;
    const int tid  = threadIdx.x;           // h
    const int tok0 = b * 16;
    const int n    = tok0 >> 10;

    __shared__ float rs[16 * RD];
    const float4* rb4 = reinterpret_cast<const float4*>(r + (size_t)tok0 * RD);
    float4* rs4 = reinterpret_cast<float4*>(rs);
    #pragma unroll
    for (int j = 0; j < 8; j++) rs4[tid + j * 128] = rb4[tid + j * 128];
    __syncthreads();

    float acc[16];
    #pragma unroll
    for (int t = 0; t < 16; t++) acc[t] = 0.f;

    const float* tb = g_t + (size_t)n * RD * HD + tid;
    for (int rr = 0; rr < RD; rr += 4) {
        const float w0  = tb[(rr + 0) * HD];
        const float w1v = tb[(rr + 1) * HD];
        const float w2v = tb[(rr + 2) * HD];
        const float w3v = tb[(rr + 3) * HD];
        #pragma unroll
        for (int t = 0; t < 16; t++) {
            float4 rv = *reinterpret_cast<const float4*>(&rs[t * RD + rr]);
            acc[t] += rv.x * w0 + rv.y * w1v + rv.z * w2v + rv.w * w3v;
        }
    }
    #pragma unroll
    for (int t = 0; t < 16; t++)
        g_vh[(size_t)(tok0 + t) * HD + tid] = __float2half_rn(fmaxf(acc[t], 0.f));
}

// ---------------------------------------------------------------------------
// Kernel C (dominant): out[t,vv] = sum_{x,h} (x[t,x]*v[t,h]) * w2[x,vv,h]
// mma.sync.m16n8k16.f16 (f32 accum). A generated per x0 as HMUL2(x-splat, v).
// 512 threads = 16 warps: 4 token-groups (32 tok, 2 m16 tiles) x 4 vv-quarters
// (16 vv). Balanced: LDS_B = 8/warp/x0, A-gen = 64 HMUL2/warp/x0, 32 MMA.
// All 128 h of v resident as packed fp16 (64 regs). Pair-stages: one barrier
// per 2 x0 (64 iters), 3 pair-buffers (96KB), cp.async prefetch distance 2.
// ---------------------------------------------------------------------------
#define XTS  132
#define KC_SMEM_DYN ((6 * 4096 + 128 * XTS) * 4)   // 96KB B bufs + 66KB x tile

#define HMUL2(d, a, b) \
    asm("mul.rn.f16x2 %0, %1, %2;" : "=r"(d) : "r"(a), "r"(b))
#define SPLAT_H2(d, f) \
    asm("cvt.rn.f16x2.f32 %0, %1, %1;" : "=r"(d) : "f"(f))
#define MMA_F16(ac, a0, a1, a2, a3, b0, b1)                                    \
    asm volatile("mma.sync.aligned.m16n8k16.row.col.f32.f16.f16.f32 "          \
        "{%0,%1,%2,%3}, {%4,%5,%6,%7}, {%8,%9}, {%0,%1,%2,%3};"                \
        : "+f"((ac)[0]), "+f"((ac)[1]), "+f"((ac)[2]), "+f"((ac)[3])           \
        : "r"(a0), "r"(a1), "r"(a2), "r"(a3), "r"(b0), "r"(b1))

__global__ __launch_bounds__(512, 1) void kC(const float* __restrict__ x) {
    extern __shared__ __align__(128) float sm[];
    float* bufs = sm;                    // 6 chunks x 4096 floats (16KB each)
    float* xs   = sm + 6 * 4096;         // 128 x XTS

    const int tid    = threadIdx.x;
    const int wid    = tid >> 5;
    const int lane   = tid & 31;
    const int g      = lane >> 2;
    const int kl     = lane & 3;
    const int split  = blockIdx.x >> 6;
    const int tile   = blockIdx.x & 63;
    const int tok0   = tile * 128;
    const int xbase  = split * 128;
    const int tokgrp = wid & 3;           // 0..3 : 32-token group (2 m16 tiles)
    const int vvq    = wid >> 2;          // 0..3 : 16-vv quarter

    uint32_t bsm;
    {
        uint64_t t0;
        asm("cvta.to.shared.u64 %0, %1;" : "=l"(t0) : "l"(bufs));
        bsm = (uint32_t)t0;
    }

    // Pair loader: 32KB (x0 = 2p, 2p+1) -> pair-slot p%3, one commit group.
    auto cpPair = [&](int p) {
        uint32_t dst = bsm + (uint32_t)(p % 3) * 32768u;
        const char* src = reinterpret_cast<const char*>(g_w2h)
                        + (size_t)(xbase + 2 * p) * 16384;
        #pragma unroll
        for (int j = 0; j < 4; j++) {
            int id = tid + j * 512;
            asm volatile("cp.async.cg.shared.global [%0], [%1], 16;"
                         :: "r"(dst + id * 16), "l"(src + id * 16) : "memory");
        }
        asm volatile("cp.async.commit_group;" ::: "memory");
    };

    cpPair(0); cpPair(1);

    // Stage x half-tile [128 tok x 128 x] (fp32, padded rows)
    {
        const float4* xg = reinterpret_cast<const float4*>(x + (size_t)tok0 * XD + xbase);
        #pragma unroll
        for (int j = 0; j < 8; j++) {
            int idx = tid + j * 512;           // 0..4095 float4
            int row = idx >> 5, c4 = idx & 31;
            *reinterpret_cast<float4*>(&xs[row * XTS + c4 * 4]) = xg[row * (XD / 4) + c4];
        }
    }

    // v fragments (fp16-packed, all 128 h): vrl/vrh[mt][rr2][ch], 64 regs
    uint32_t vrl[2][2][8], vrh[2][2][8];
    #pragma unroll
    for (int mt = 0; mt < 2; mt++)
        #pragma unroll
        for (int rr2 = 0; rr2 < 2; rr2++) {
            int row = tok0 + tokgrp * 32 + mt * 16 + rr2 * 8 + g;
            const uint32_t* vp = reinterpret_cast<const uint32_t*>(g_vh + (size_t)row * HD);
            #pragma unroll
            for (int ch = 0; ch < 8; ch++) {
                vrl[mt][rr2][ch] = vp[ch * 8 + kl];       // h = ch*16 + kl*2, +1
                vrh[mt][rr2][ch] = vp[ch * 8 + kl + 4];   // h = ch*16 + kl*2+8, +9
            }
        }

    float acc[2][2][4];                   // [mt][nt][reg]
    #pragma unroll
    for (int mt = 0; mt < 2; mt++)
        #pragma unroll
        for (int nt = 0; nt < 2; nt++)
            #pragma unroll
            for (int q = 0; q < 4; q++) acc[mt][nt][q] = 0.f;

    const int xr00 = (tokgrp * 32 +      g) * XTS;    // mt0 rr0
    const int xr01 = (tokgrp * 32 +  8 + g) * XTS;    // mt0 rr1
    const int xr10 = (tokgrp * 32 + 16 + g) * XTS;    // mt1 rr0
    const int xr11 = (tokgrp * 32 + 24 + g) * XTS;    // mt1 rr1

    for (int p = 0; p < 64; p++) {
        asm volatile("cp.async.wait_group 1;" ::: "memory");
        __syncthreads();
        if (p + 2 < 64) cpPair(p + 2);
        else asm volatile("cp.async.commit_group;" ::: "memory");  // keep accounting

        const float* pairbase = bufs + (p % 3) * 8192;
        #pragma unroll
        for (int sub = 0; sub < 2; sub++) {
            const int x0 = 2 * p + sub;
            const uint4* Bq = reinterpret_cast<const uint4*>(pairbase + sub * 4096);
            uint32_t xp00, xp01, xp10, xp11;
            SPLAT_H2(xp00, xs[xr00 + x0]);
            SPLAT_H2(xp01, xs[xr01 + x0]);
            SPLAT_H2(xp10, xs[xr10 + x0]);
            SPLAT_H2(xp11, xs[xr11 + x0]);

            #pragma unroll
            for (int hcp = 0; hcp < 4; hcp++) {
                uint32_t A[2][2][4];                 // [cc][mt][reg]
                #pragma unroll
                for (int cc = 0; cc < 2; cc++) {
                    int ch = hcp * 2 + cc;
                    HMUL2(A[cc][0][0], xp00, vrl[0][0][ch]);
                    HMUL2(A[cc][0][1], xp01, vrl[0][1][ch]);
                    HMUL2(A[cc][0][2], xp00, vrh[0][0][ch]);
                    HMUL2(A[cc][0][3], xp01, vrh[0][1][ch]);
                    HMUL2(A[cc][1][0], xp10, vrl[1][0][ch]);
                    HMUL2(A[cc][1][1], xp11, vrl[1][1][ch]);
                    HMUL2(A[cc][1][2], xp10, vrh[1][0][ch]);
                    HMUL2(A[cc][1][3], xp11, vrh[1][1][ch]);
                }
                #pragma unroll
                for (int nt = 0; nt < 2; nt++) {
                    uint4 Bv = Bq[hcp * 256 + (vvq * 16 + nt * 8 + g) * 4 + kl];
                    MMA_F16(acc[0][nt], A[0][0][0], A[0][0][1], A[0][0][2], A[0][0][3], Bv.x, Bv.y);
                    MMA_F16(acc[1][nt], A[0][1][0], A[0][1][1], A[0][1][2], A[0][1][3], Bv.x, Bv.y);
                    MMA_F16(acc[0][nt], A[1][0][0], A[1][0][1], A[1][0][2], A[1][0][3], Bv.z, Bv.w);
                    MMA_F16(acc[1][nt], A[1][1][0], A[1][1][1], A[1][1][2], A[1][1][3], Bv.z, Bv.w);
                }
            }
        }
    }

    // Epilogue: partials (still scaled by 1024; kD rescales)
    float* pp = g_part[split];
    #pragma unroll
    for (int mt = 0; mt < 2; mt++) {
        int r0 = tok0 + tokgrp * 32 + mt * 16 + g;
        #pragma unroll
        for (int nt = 0; nt < 2; nt++) {
            int col = vvq * 16 + nt * 8 + kl * 2;
            *reinterpret_cast<float2*>(&pp[(size_t)r0 * VD + col]) =
                make_float2(acc[mt][nt][0], acc[mt][nt][1]);
            *reinterpret_cast<float2*>(&pp[(size_t)(r0 + 8) * VD + col]) =
                make_float2(acc[mt][nt][2], acc[mt][nt][3]);
        }
    }
}

// ---------------------------------------------------------------------------
// Kernel D: out = (part0 + part1) * 2^-10  (undo exact w2 prescale)
// ---------------------------------------------------------------------------
__global__ void kD(float* __restrict__ out) {
    const float S = 1.0f / 1024.0f;
    int i = blockIdx.x * 256 + threadIdx.x;   // float4 index
    float4 a = reinterpret_cast<const float4*>(g_part[0])[i];
    float4 b = reinterpret_cast<const float4*>(g_part[1])[i];
    float4 o;
    o.x = (a.x + b.x) * S; o.y = (a.y + b.y) * S;
    o.z = (a.z + b.z) * S; o.w = (a.w + b.w) * S;
    reinterpret_cast<float4*>(out)[i] = o;
}

// ---------------------------------------------------------------------------
extern "C" void kernel_launch(void* const* d_in, const int* in_sizes, int n_in,
                              void* d_out, int out_size) {
    const float* x  = (const float*)d_in[0];
    const float* r  = (const float*)d_in[1];
    const float* u  = (const float*)d_in[2];
    const float* w1 = (const float*)d_in[3];
    const float* w2 = (const float*)d_in[4];
    float* out = (float*)d_out;

    cudaFuncSetAttribute(kC, cudaFuncAttributeMaxDynamicSharedMemorySize, KC_SMEM_DYN);

    kW<<<(XD * VD * HD) / (256 * 8), 256>>>(w2);   // 1024 blocks, 1 STG.128/thread
    kA<<<NB * RD, 256>>>(u, w1);
    kB<<<NTOK / 16, 128>>>(r);
    kC<<<128, 512, KC_SMEM_DYN>>>(x);
    kD<<<(NTOK * VD) / 1024, 256>>>(out);
}

// round 12
// speedup vs baseline: 2.0139x; 1.0582x over previous
#include <cuda_runtime.h>
#include <cuda_fp16.h>
#include <cstdint>

// Shapes
#define NB   8
#define NTOK 8192      // N * I * J
#define XD   256
#define RD   256
#define UD   64
#define VD   64
#define HD   128

// Scratch (allocation-free: __device__ globals)
__device__ __half   g_th[NB * HD * RD];      // t[n,h,r] fp16 TRANSPOSED (r contiguous)
__device__ __half   g_vh[NTOK * HD];         // v[tok,h] fp16
__device__ __half   g_w2h[XD * VD * HD];     // fragment-packed fp16 w2 * 1024 (4MB)
__device__ float    g_part[2][NTOK * VD];    // K-split partials (scaled by 1024)
__device__ unsigned g_cnt[64];               // per-tile arrival counters (self-resetting)

#define PACKS_H2(d, lo, hi) /* d = fp16x2 {lo,hi} * 1024 */                    \
    asm("cvt.rn.f16x2.f32 %0, %1, %2;" : "=r"(d) : "f"((hi) * 1024.0f), "f"((lo) * 1024.0f))
#define PACK_H2(d, lo, hi)  /* d = fp16x2 {lo,hi} */                           \
    asm("cvt.rn.f16x2.f32 %0, %1, %2;" : "=r"(d) : "f"(hi), "f"(lo))
#define HMUL2(d, a, b) \
    asm("mul.rn.f16x2 %0, %1, %2;" : "=r"(d) : "r"(a), "r"(b))
#define SPLAT_H2(d, f) \
    asm("cvt.rn.f16x2.f32 %0, %1, %1;" : "=r"(d) : "f"(f))
#define MMA_F16(ac, a0, a1, a2, a3, b0, b1)                                    \
    asm volatile("mma.sync.aligned.m16n8k16.row.col.f32.f16.f16.f32 "          \
        "{%0,%1,%2,%3}, {%4,%5,%6,%7}, {%8,%9}, {%0,%1,%2,%3};"                \
        : "+f"((ac)[0]), "+f"((ac)[1]), "+f"((ac)[2]), "+f"((ac)[3])           \
        : "r"(a0), "r"(a1), "r"(a2), "r"(a3), "r"(b0), "r"(b1))

extern __shared__ __align__(128) char g_smem_raw[];

// ---------------------------------------------------------------------------
// Kernel W: fragment-pack w2 for kC (fp16, scaled by 2^10 exact).
// One thread = one (x0, vv, hcp, kl) -> one coalesced STG.128 of 8 halves.
// Byte addr = x0*16384 + hcp*4096 + vv*64 + kl*16; slot = codd*4+breg*2+dlt,
// h = hcp*32 + codd*16 + breg*8 + kl*2 + dlt.
// ---------------------------------------------------------------------------
__global__ void kW(const float* __restrict__ w2) {
    int gid = blockIdx.x * 256 + threadIdx.x;     // 0 .. 262143
    int kl  = gid & 3;
    int hcp = (gid >> 2) & 3;
    int vv  = (gid >> 4) & 63;
    int x0  = gid >> 10;

    const float* src = w2 + (size_t)x0 * (VD * HD) + (size_t)vv * HD;
    uint4 o;
    {
        int hb = hcp * 32 + kl * 2;
        float2 a = *reinterpret_cast<const float2*>(src + hb);
        float2 b = *reinterpret_cast<const float2*>(src + hb + 8);
        float2 c = *reinterpret_cast<const float2*>(src + hb + 16);
        float2 d = *reinterpret_cast<const float2*>(src + hb + 24);
        PACKS_H2(o.x, a.x, a.y);
        PACKS_H2(o.y, b.x, b.y);
        PACKS_H2(o.z, c.x, c.y);
        PACKS_H2(o.w, d.x, d.y);
    }
    char* dst = reinterpret_cast<char*>(g_w2h)
              + (size_t)x0 * 16384 + hcp * 4096 + vv * 64 + kl * 16;
    *reinterpret_cast<uint4*>(dst) = o;
}

// ---------------------------------------------------------------------------
// Kernel A: t[n,r,h] = sum_u ( sum_v u[n,r,u,v] ) * w1[r,u,h]
// 256 blocks (one per r), looping the 8 n's (fewer wave transitions).
// Writes t as fp16 TRANSPOSED to g_th[n][h][r] for kB's B-fragments.
// ---------------------------------------------------------------------------
#define UAS 68
__global__ void kA(const float* __restrict__ u, const float* __restrict__ w1) {
    const int rr  = blockIdx.x;
    const int tid = threadIdx.x;            // 0..255

    __shared__ float us[UD * UAS];
    __shared__ float s[2][UD];

    const float* w1b = w1 + (size_t)rr * UD * HD + (tid & 127);

    for (int n = 0; n < NB; n++) {
        const float4* ub4 = reinterpret_cast<const float4*>(
            u + (size_t)(n * RD + rr) * (UD * VD));
        #pragma unroll
        for (int j = 0; j < 4; j++) {
            int idx = tid + j * 256;        // 0..1023 float4
            int row = idx >> 4, col = idx & 15;
            *reinterpret_cast<float4*>(&us[row * UAS + col * 4]) = ub4[idx];
        }
        __syncthreads();

        {   // Phase 1: sum over v (64) -> s[n&1][u]
            int uu = tid >> 2, part = tid & 3;
            const float4* p4 = reinterpret_cast<const float4*>(&us[uu * UAS + part * 16]);
            float4 a = p4[0], b = p4[1], c = p4[2], d = p4[3];
            float sum = ((a.x + a.y) + (a.z + a.w)) + ((b.x + b.y) + (b.z + b.w))
                      + ((c.x + c.y) + (c.z + c.w)) + ((d.x + d.y) + (d.z + d.w));
            sum += __shfl_xor_sync(0xffffffffu, sum, 1);
            sum += __shfl_xor_sync(0xffffffffu, sum, 2);
            if (part == 0) s[n & 1][uu] = sum;
        }
        __syncthreads();

        if (tid < HD) {   // Phase 2: t[h] = sum_u s[u] * w1[r,u,h]  -> fp16 transposed
            const float* ss = s[n & 1];
            float a0 = 0.f, a1 = 0.f, a2 = 0.f, a3 = 0.f;
            #pragma unroll 4
            for (int uu = 0; uu < UD; uu += 4) {
                a0 += ss[uu + 0] * w1b[(uu + 0) * HD];
                a1 += ss[uu + 1] * w1b[(uu + 1) * HD];
                a2 += ss[uu + 2] * w1b[(uu + 2) * HD];
                a3 += ss[uu + 3] * w1b[(uu + 3) * HD];
            }
            g_th[((size_t)n * HD + tid) * RD + rr] =
                __float2half_rn((a0 + a1) + (a2 + a3));
        }
        // next staging overwrites us: safe (phase1 consumed it; phase2 reads only s/w1;
        // s double-buffered across n)
    }
}

// ---------------------------------------------------------------------------
// Kernel B: v[tok,h] = relu( sum_r r[tok,rr] * t[n,rr,h] ) -> fp16, via
// mma.sync.m16n8k16.f16 (f32 accum). Grid 128 = 64 token-tiles x 2 h-halves.
// 512 threads = 8 token-groups(16 tok) x 2 h32. A = r fp16 (packed in smem),
// B = t fp16 from g_th[n][h][r] (r contiguous -> u32 pairs). K=256 = 16 steps.
// ---------------------------------------------------------------------------
#define KB_SMEM ((128 * 132 + 64 * 132) * 4)   // rsh + tsh (u32), padded stride 132

__global__ __launch_bounds__(512, 1) void kB(const float* __restrict__ r) {
    uint32_t* rsh = reinterpret_cast<uint32_t*>(g_smem_raw);           // [128][132]
    uint32_t* tsh = rsh + 128 * 132;                                   // [64][132]

    const int tid  = threadIdx.x;
    const int wid  = tid >> 5;
    const int lane = tid & 31;
    const int g    = lane >> 2;
    const int kl   = lane & 3;
    const int tile = blockIdx.x >> 1;
    const int hh   = blockIdx.x & 1;
    const int tok0 = tile * 128;
    const int hbase = hh * 64;
    const int n    = tok0 >> 10;
    const int tokgrp = wid >> 1;       // 0..7
    const int h32    = wid & 1;        // 0/1 : 32-h half of this block's 64 h

    // Stage r tile [128 tok][256 r] fp32 -> fp16 pairs
    const float4* rg = reinterpret_cast<const float4*>(r + (size_t)tok0 * RD);
    #pragma unroll
    for (int j = 0; j < 16; j++) {
        int idx = tid + j * 512;           // 0..8191 float4
        int row = idx >> 6, c4 = idx & 63;
        float4 v = rg[idx];
        uint32_t p0, p1;
        PACK_H2(p0, v.x, v.y);
        PACK_H2(p1, v.z, v.w);
        *reinterpret_cast<uint2*>(&rsh[row * 132 + c4 * 2]) = make_uint2(p0, p1);
    }
    // Stage t slice [64 h][256 r] as u32 pairs (coalesced from g_th)
    const uint32_t* tg = reinterpret_cast<const uint32_t*>(g_th)
                       + ((size_t)n * HD + hbase) * (RD / 2);
    #pragma unroll
    for (int j = 0; j < 16; j++) {
        int idx = tid + j * 512;           // 0..8191 u32
        int hl = idx >> 7, rr2 = idx & 127;
        tsh[hl * 132 + rr2] = tg[hl * (RD / 2) + rr2];
    }
    __syncthreads();

    float acc[4][4];
    #pragma unroll
    for (int nt = 0; nt < 4; nt++)
        #pragma unroll
        for (int q = 0; q < 4; q++) acc[nt][q] = 0.f;

    const int arow0 = (tokgrp * 16 + g) * 132;
    const int arow1 = (tokgrp * 16 + 8 + g) * 132;

    #pragma unroll
    for (int ks = 0; ks < 16; ks++) {
        uint32_t a0 = rsh[arow0 + ks * 8 + kl];
        uint32_t a1 = rsh[arow1 + ks * 8 + kl];
        uint32_t a2 = rsh[arow0 + ks * 8 + kl + 4];
        uint32_t a3 = rsh[arow1 + ks * 8 + kl + 4];
        #pragma unroll
        for (int nt = 0; nt < 4; nt++) {
            int hl = h32 * 32 + nt * 8 + g;
            uint32_t b0 = tsh[hl * 132 + ks * 8 + kl];
            uint32_t b1 = tsh[hl * 132 + ks * 8 + kl + 4];
            MMA_F16(acc[nt], a0, a1, a2, a3, b0, b1);
        }
    }

    // relu + pack + store v (row-major [tok][h] fp16, u32 granularity)
    uint32_t* vout = reinterpret_cast<uint32_t*>(g_vh);
    #pragma unroll
    for (int nt = 0; nt < 4; nt++) {
        int col32 = (hbase >> 1) + h32 * 16 + nt * 4 + kl;
        int row   = tok0 + tokgrp * 16 + g;
        uint32_t pl, ph;
        PACK_H2(pl, fmaxf(acc[nt][0], 0.f), fmaxf(acc[nt][1], 0.f));
        PACK_H2(ph, fmaxf(acc[nt][2], 0.f), fmaxf(acc[nt][3], 0.f));
        vout[(size_t)row * (HD / 2) + col32]       = pl;
        vout[(size_t)(row + 8) * (HD / 2) + col32] = ph;
    }
}

// ---------------------------------------------------------------------------
// Kernel C (dominant): out[t,vv] = sum_{x,h} (x[t,x]*v[t,h]) * w2[x,vv,h]
// mma.sync.m16n8k16.f16 (f32 accum), A regenerated per x0 (rank-1, HMUL2).
// 512 threads = 4 token-groups x 4 vv-quarters; pair-stages, 3 pair-buffers.
// Fused combine: last-arriving split per tile adds peer partials (from this
// block's own register positions) and writes out (IEEE a+b commutative ->
// bitwise deterministic). Counter self-resets for graph replay.
// ---------------------------------------------------------------------------
#define XTS  132
#define KC_SMEM_DYN ((6 * 4096 + 128 * XTS) * 4)   // 96KB B bufs + 66KB x tile

__global__ __launch_bounds__(512, 1) void kC(const float* __restrict__ x,
                                             float* __restrict__ out) {
    float* sm   = reinterpret_cast<float*>(g_smem_raw);
    float* bufs = sm;                    // 6 chunks x 4096 floats (16KB each)
    float* xs   = sm + 6 * 4096;         // 128 x XTS
    __shared__ unsigned s_last;

    const int tid    = threadIdx.x;
    const int wid    = tid >> 5;
    const int lane   = tid & 31;
    const int g      = lane >> 2;
    const int kl     = lane & 3;
    const int split  = blockIdx.x >> 6;
    const int tile   = blockIdx.x & 63;
    const int tok0   = tile * 128;
    const int xbase  = split * 128;
    const int tokgrp = wid & 3;           // 0..3 : 32-token group (2 m16 tiles)
    const int vvq    = wid >> 2;          // 0..3 : 16-vv quarter

    uint32_t bsm;
    {
        uint64_t t0;
        asm("cvta.to.shared.u64 %0, %1;" : "=l"(t0) : "l"(bufs));
        bsm = (uint32_t)t0;
    }

    auto cpPair = [&](int p) {
        uint32_t dst = bsm + (uint32_t)(p % 3) * 32768u;
        const char* src = reinterpret_cast<const char*>(g_w2h)
                        + (size_t)(xbase + 2 * p) * 16384;
        #pragma unroll
        for (int j = 0; j < 4; j++) {
            int id = tid + j * 512;
            asm volatile("cp.async.cg.shared.global [%0], [%1], 16;"
                         :: "r"(dst + id * 16), "l"(src + id * 16) : "memory");
        }
        asm volatile("cp.async.commit_group;" ::: "memory");
    };

    cpPair(0); cpPair(1);

    {
        const float4* xg = reinterpret_cast<const float4*>(x + (size_t)tok0 * XD + xbase);
        #pragma unroll
        for (int j = 0; j < 8; j++) {
            int idx = tid + j * 512;           // 0..4095 float4
            int row = idx >> 5, c4 = idx & 31;
            *reinterpret_cast<float4*>(&xs[row * XTS + c4 * 4]) = xg[row * (XD / 4) + c4];
        }
    }

    uint32_t vrl[2][2][8], vrh[2][2][8];
    #pragma unroll
    for (int mt = 0; mt < 2; mt++)
        #pragma unroll
        for (int rr2 = 0; rr2 < 2; rr2++) {
            int row = tok0 + tokgrp * 32 + mt * 16 + rr2 * 8 + g;
            const uint32_t* vp = reinterpret_cast<const uint32_t*>(g_vh + (size_t)row * HD);
            #pragma unroll
            for (int ch = 0; ch < 8; ch++) {
                vrl[mt][rr2][ch] = vp[ch * 8 + kl];
                vrh[mt][rr2][ch] = vp[ch * 8 + kl + 4];
            }
        }

    float acc[2][2][4];
    #pragma unroll
    for (int mt = 0; mt < 2; mt++)
        #pragma unroll
        for (int nt = 0; nt < 2; nt++)
            #pragma unroll
            for (int q = 0; q < 4; q++) acc[mt][nt][q] = 0.f;

    const int xr00 = (tokgrp * 32 +      g) * XTS;
    const int xr01 = (tokgrp * 32 +  8 + g) * XTS;
    const int xr10 = (tokgrp * 32 + 16 + g) * XTS;
    const int xr11 = (tokgrp * 32 + 24 + g) * XTS;

    for (int p = 0; p < 64; p++) {
        asm volatile("cp.async.wait_group 1;" ::: "memory");
        __syncthreads();
        if (p + 2 < 64) cpPair(p + 2);
        else asm volatile("cp.async.commit_group;" ::: "memory");

        const float* pairbase = bufs + (p % 3) * 8192;
        #pragma unroll
        for (int sub = 0; sub < 2; sub++) {
            const int x0 = 2 * p + sub;
            const uint4* Bq = reinterpret_cast<const uint4*>(pairbase + sub * 4096);
            uint32_t xp00, xp01, xp10, xp11;
            SPLAT_H2(xp00, xs[xr00 + x0]);
            SPLAT_H2(xp01, xs[xr01 + x0]);
            SPLAT_H2(xp10, xs[xr10 + x0]);
            SPLAT_H2(xp11, xs[xr11 + x0]);

            #pragma unroll
            for (int hcp = 0; hcp < 4; hcp++) {
                uint32_t A[2][2][4];
                #pragma unroll
                for (int cc = 0; cc < 2; cc++) {
                    int ch = hcp * 2 + cc;
                    HMUL2(A[cc][0][0], xp00, vrl[0][0][ch]);
                    HMUL2(A[cc][0][1], xp01, vrl[0][1][ch]);
                    HMUL2(A[cc][0][2], xp00, vrh[0][0][ch]);
                    HMUL2(A[cc][0][3], xp01, vrh[0][1][ch]);
                    HMUL2(A[cc][1][0], xp10, vrl[1][0][ch]);
                    HMUL2(A[cc][1][1], xp11, vrl[1][1][ch]);
                    HMUL2(A[cc][1][2], xp10, vrh[1][0][ch]);
                    HMUL2(A[cc][1][3], xp11, vrh[1][1][ch]);
                }
                #pragma unroll
                for (int nt = 0; nt < 2; nt++) {
                    uint4 Bv = Bq[hcp * 256 + (vvq * 16 + nt * 8 + g) * 4 + kl];
                    MMA_F16(acc[0][nt], A[0][0][0], A[0][0][1], A[0][0][2], A[0][0][3], Bv.x, Bv.y);
                    MMA_F16(acc[1][nt], A[0][1][0], A[0][1][1], A[0][1][2], A[0][1][3], Bv.x, Bv.y);
                    MMA_F16(acc[0][nt], A[1][0][0], A[1][0][1], A[1][0][2], A[1][0][3], Bv.z, Bv.w);
                    MMA_F16(acc[1][nt], A[1][1][0], A[1][1][1], A[1][1][2], A[1][1][3], Bv.z, Bv.w);
                }
            }
        }
    }

    // Write own partials (scaled by 1024)
    float* pp = g_part[split];
    #pragma unroll
    for (int mt = 0; mt < 2; mt++) {
        int r0 = tok0 + tokgrp * 32 + mt * 16 + g;
        #pragma unroll
        for (int nt = 0; nt < 2; nt++) {
            int col = vvq * 16 + nt * 8 + kl * 2;
            *reinterpret_cast<float2*>(&pp[(size_t)r0 * VD + col]) =
                make_float2(acc[mt][nt][0], acc[mt][nt][1]);
            *reinterpret_cast<float2*>(&pp[(size_t)(r0 + 8) * VD + col]) =
                make_float2(acc[mt][nt][2], acc[mt][nt][3]);
        }
    }

    // Fused combine: last split per tile sums and writes out
    __threadfence();
    __syncthreads();
    if (tid == 0) s_last = atomicAdd(&g_cnt[tile], 1);
    __syncthreads();
    if (s_last == 1) {
        __threadfence();
        const float S = 1.0f / 1024.0f;
        const float* peer = g_part[1 - split];
        #pragma unroll
        for (int mt = 0; mt < 2; mt++) {
            int r0 = tok0 + tokgrp * 32 + mt * 16 + g;
            #pragma unroll
            for (int nt = 0; nt < 2; nt++) {
                int col = vvq * 16 + nt * 8 + kl * 2;
                float2 q0 = *reinterpret_cast<const float2*>(&peer[(size_t)r0 * VD + col]);
                float2 q1 = *reinterpret_cast<const float2*>(&peer[(size_t)(r0 + 8) * VD + col]);
                *reinterpret_cast<float2*>(&out[(size_t)r0 * VD + col]) =
                    make_float2((acc[mt][nt][0] + q0.x) * S, (acc[mt][nt][1] + q0.y) * S);
                *reinterpret_cast<float2*>(&out[(size_t)(r0 + 8) * VD + col]) =
                    make_float2((acc[mt][nt][2] + q1.x) * S, (acc[mt][nt][3] + q1.y) * S);
            }
        }
        if (tid == 0) g_cnt[tile] = 0;   // self-reset for next launch/replay
    }
}

// ---------------------------------------------------------------------------
extern "C" void kernel_launch(void* const* d_in, const int* in_sizes, int n_in,
                              void* d_out, int out_size) {
    const float* x  = (const float*)d_in[0];
    const float* r  = (const float*)d_in[1];
    const float* u  = (const float*)d_in[2];
    const float* w1 = (const float*)d_in[3];
    const float* w2 = (const float*)d_in[4];
    float* out = (float*)d_out;

    cudaFuncSetAttribute(kC, cudaFuncAttributeMaxDynamicSharedMemorySize, KC_SMEM_DYN);
    cudaFuncSetAttribute(kB, cudaFuncAttributeMaxDynamicSharedMemorySize, KB_SMEM);

    kW<<<(XD * VD * HD) / (256 * 8), 256>>>(w2);
    kA<<<RD, 256>>>(u, w1);
    kB<<<NTOK / 64, 512, KB_SMEM>>>(r);        // 128 blocks: 64 tiles x 2 h-halves
    kC<<<128, 512, KC_SMEM_DYN>>>(x, out);
}